// round 7
// baseline (speedup 1.0000x reference)
#include <cuda_runtime.h>

// StateQueue: pure data movement. Shapes fixed.
#define Bv   16
#define Nv   900
#define Dv   256
#define QMv  4
#define QPv  4
#define NPv  6
#define Tv   4
#define TM1v 3

// Region sizes (float elements)
#define S_MQ  (Bv*QMv*Nv*Dv)   /* 3,686,400 */
#define S_PQ  (Bv*QPv*NPv*Dv)  /*    98,304 */
#define S_EQ  (Bv*QPv*Dv)      /*    16,384 */
#define S_PER (Bv*QMv)         /*        64 */
#define S_MM  (Bv*TM1v*Nv)     /*    43,200 */
#define S_ME  (Bv*TM1v*Nv*Dv)  /* 11,059,200 */
#define S_PM  (Bv*TM1v)        /*        48 */
#define S_PE  (Bv*TM1v*Dv)     /*    12,288 */

// Output offsets
#define O_MQ  0
#define O_PQ  (O_MQ + S_MQ)
#define O_EQ  (O_PQ + S_PQ)
#define O_PER (O_EQ + S_EQ)
#define O_MM  (O_PER + S_PER)
#define O_ME  (O_MM + S_MM)
#define O_PM  (O_ME + S_ME)
#define O_PE  (O_PM + S_PM)

// Per-virtual-block chunk: 256 threads x 4 float4 = 4096 floats (16 KB)
#define KITER 4
#define CHUNK (256 * KITER * 4)

#define B_MQ  (S_MQ / CHUNK)              /* 900 exact  */
#define B_PQ  (S_PQ / CHUNK)              /* 24 exact   */
#define B_EQ  (S_EQ / CHUNK)              /* 4 exact    */
#define B_PER 1
#define B_MM  ((S_MM + CHUNK - 1)/CHUNK)  /* 11, tail   */
#define B_ME  (S_ME / CHUNK)              /* 2700 exact */
#define B_PM  1
#define B_PE  (S_PE / CHUNK)              /* 3 exact    */

#define E_MQ  (B_MQ)
#define E_PQ  (E_MQ + B_PQ)
#define E_EQ  (E_PQ + B_EQ)
#define E_PER (E_EQ + B_PER)
#define E_MM  (E_PER + B_MM)
#define E_ME  (E_MM + B_ME)
#define E_PM  (E_ME + B_PM)
#define E_PE  (E_PM + B_PE)
#define NVBLOCKS E_PE

// Persistent grid: 148 SMs x 8 blocks (regs<=32, 256 thr -> 8 CTA/SM)
#define NPHYS (148 * 8)

__global__ __launch_bounds__(256) void state_queue_kernel(
    const float* __restrict__ motion_query,      // (B,N,D)
    const float* __restrict__ plan_query,        // (B,NP,D)
    const float* __restrict__ ego_status,        // (B,D)
    const float* __restrict__ motion_queue,      // (B,QM,N,D)
    const float* __restrict__ plan_queue,        // (B,QP,NP,D)
    const float* __restrict__ ego_status_queue,  // (B,QP,D)
    const int*   __restrict__ period,            // (B,QM)
    const int*   __restrict__ mask,              // (B,) bool->int32
    const float* __restrict__ tae,               // (B,N,T,D)
    const int*   __restrict__ tm,                // (B,N,T) bool->int32
    const float* __restrict__ etae,              // (B,1,T,D)
    const int*   __restrict__ etm,               // (B,1,T) bool->int32
    float* __restrict__ out)
{
    const int tid = threadIdx.x;

    for (int blk = blockIdx.x; blk < NVBLOCKS; blk += gridDim.x) {

    if (blk < E_MQ) {
        // ---- mq: (b,q,n,d) = keep ? motion_queue : motion_query[b,n,d]
        const int base = blk * CHUNK;
        float4 v[KITER];
        #pragma unroll
        for (int k = 0; k < KITER; k++) {
            int e = base + (k * 256 + tid) * 4;
            int d = e & (Dv - 1);
            int r = e >> 8;
            int n = r % Nv;
            int b = r / (Nv * QMv);
            const float* src = (mask[b] != 0)
                ? &motion_queue[e]
                : &motion_query[(b * Nv + n) * Dv + d];
            v[k] = *reinterpret_cast<const float4*>(src);
        }
        #pragma unroll
        for (int k = 0; k < KITER; k++) {
            int e = base + (k * 256 + tid) * 4;
            *reinterpret_cast<float4*>(&out[O_MQ + e]) = v[k];
        }
    } else if (blk < E_PQ) {
        // ---- pq
        const int base = (blk - E_MQ) * CHUNK;
        float4 v[KITER];
        #pragma unroll
        for (int k = 0; k < KITER; k++) {
            int e = base + (k * 256 + tid) * 4;
            int d = e & (Dv - 1);
            int r = e >> 8;
            int np = r % NPv;
            int b = r / (NPv * QPv);
            const float* src = (mask[b] != 0)
                ? &plan_queue[e]
                : &plan_query[(b * NPv + np) * Dv + d];
            v[k] = *reinterpret_cast<const float4*>(src);
        }
        #pragma unroll
        for (int k = 0; k < KITER; k++) {
            int e = base + (k * 256 + tid) * 4;
            *reinterpret_cast<float4*>(&out[O_PQ + e]) = v[k];
        }
    } else if (blk < E_EQ) {
        // ---- eq
        const int base = (blk - E_PQ) * CHUNK;
        float4 v[KITER];
        #pragma unroll
        for (int k = 0; k < KITER; k++) {
            int e = base + (k * 256 + tid) * 4;
            int d = e & (Dv - 1);
            int b = (e >> 8) / QPv;
            const float* src = (mask[b] != 0)
                ? &ego_status_queue[e]
                : &ego_status[b * Dv + d];
            v[k] = *reinterpret_cast<const float4*>(src);
        }
        #pragma unroll
        for (int k = 0; k < KITER; k++) {
            int e = base + (k * 256 + tid) * 4;
            *reinterpret_cast<float4*>(&out[O_EQ + e]) = v[k];
        }
    } else if (blk < E_PER) {
        // ---- per: 64 elems, QM=4 per b
        int e = tid * 4;
        if (e < S_PER) {
            int b = e >> 2;  // QM = 4
            bool keep = (mask[b] != 0);
            float4 v;
            v.x = keep ? (float)period[e + 0] : 0.0f;
            v.y = keep ? (float)period[e + 1] : 0.0f;
            v.z = keep ? (float)period[e + 2] : 0.0f;
            v.w = keep ? (float)period[e + 3] : 0.0f;
            *reinterpret_cast<float4*>(&out[O_PER + e]) = v;
        }
    } else if (blk < E_MM) {
        // ---- mm: out[b][t][n] = tm[b][n][t]
        const int base = (blk - E_PER) * CHUNK;
        #pragma unroll
        for (int k = 0; k < KITER; k++) {
            int e = base + (k * 256 + tid) * 4;
            if (e < S_MM) {
                int n = e % Nv;             // N divisible by 4: same t,b for 4
                int r = e / Nv;
                int t = r % TM1v;
                int b = r / TM1v;
                int src = (b * Nv + n) * Tv + t;
                float4 v;
                v.x = tm[src + 0 * Tv] ? 1.0f : 0.0f;
                v.y = tm[src + 1 * Tv] ? 1.0f : 0.0f;
                v.z = tm[src + 2 * Tv] ? 1.0f : 0.0f;
                v.w = tm[src + 3 * Tv] ? 1.0f : 0.0f;
                *reinterpret_cast<float4*>(&out[O_MM + e]) = v;
            }
        }
    } else if (blk < E_ME) {
        // ---- me: out[b][t][n][d] = tae[b][n][t][d]
        const int base = (blk - E_MM) * CHUNK;
        float4 v[KITER];
        #pragma unroll
        for (int k = 0; k < KITER; k++) {
            int e = base + (k * 256 + tid) * 4;
            int d = e & (Dv - 1);
            int r = e >> 8;
            int n = r % Nv;
            int t = (r / Nv) % TM1v;
            int b = r / (Nv * TM1v);
            v[k] = *reinterpret_cast<const float4*>(
                &tae[((b * Nv + n) * Tv + t) * Dv + d]);
        }
        #pragma unroll
        for (int k = 0; k < KITER; k++) {
            int e = base + (k * 256 + tid) * 4;
            *reinterpret_cast<float4*>(&out[O_ME + e]) = v[k];
        }
    } else if (blk < E_PM) {
        // ---- pm: 48 elems, out[b][t] = etm[b][t]
        int e = tid * 4;
        if (e < S_PM) {
            float vv[4];
            #pragma unroll
            for (int j = 0; j < 4; j++) {
                int idx = e + j;
                int t = idx % TM1v;
                int b = idx / TM1v;
                vv[j] = etm[b * Tv + t] ? 1.0f : 0.0f;
            }
            float4 v = {vv[0], vv[1], vv[2], vv[3]};
            *reinterpret_cast<float4*>(&out[O_PM + e]) = v;
        }
    } else {
        // ---- pe: out[b][t][0][d] with any/all/argmin overwrite
        const int base = (blk - E_PM) * CHUNK;
        bool anyf = false;
        #pragma unroll
        for (int bb = 0; bb < Bv; bb++)
            #pragma unroll
            for (int tt = 0; tt < TM1v; tt++)
                anyf = anyf || (etm[bb * Tv + tt] != 0);
        #pragma unroll
        for (int k = 0; k < KITER; k++) {
            int e = base + (k * 256 + tid) * 4;
            int d = e & (Dv - 1);
            int r = e >> 8;
            int t = r % TM1v;
            int b = r / TM1v;
            bool m0 = etm[b * Tv + 0] != 0;
            bool m1 = etm[b * Tv + 1] != 0;
            bool m2 = etm[b * Tv + 2] != 0;
            bool all_true = m0 && m1 && m2;
            int ff = (!m0) ? 0 : ((!m1) ? 1 : ((!m2) ? 2 : 0));
            bool overwrite = all_true || (t < ff);
            int src_t = (anyf && overwrite) ? (all_true ? (Tv - 1) : ff) : t;
            float4 v = *reinterpret_cast<const float4*>(
                &etae[(b * Tv + src_t) * Dv + d]);
            *reinterpret_cast<float4*>(&out[O_PE + e]) = v;
        }
    }

    } // grid-stride loop
}

extern "C" void kernel_launch(void* const* d_in, const int* in_sizes, int n_in,
                              void* d_out, int out_size) {
    const float* motion_query     = (const float*)d_in[0];
    const float* plan_query       = (const float*)d_in[1];
    const float* ego_status       = (const float*)d_in[2];
    const float* motion_queue     = (const float*)d_in[3];
    const float* plan_queue       = (const float*)d_in[4];
    const float* ego_status_queue = (const float*)d_in[5];
    const int*   period           = (const int*)d_in[6];
    const int*   mask             = (const int*)d_in[7];
    const float* tae              = (const float*)d_in[8];
    const int*   tm               = (const int*)d_in[9];
    const float* etae             = (const float*)d_in[10];
    const int*   etm              = (const int*)d_in[11];
    float* out = (float*)d_out;

    state_queue_kernel<<<NPHYS, 256>>>(
        motion_query, plan_query, ego_status, motion_queue, plan_queue,
        ego_status_queue, period, mask, tae, tm, etae, etm, out);
}

// round 8
// speedup vs baseline: 1.1178x; 1.1178x over previous
#include <cuda_runtime.h>

// StateQueue: pure data movement. Shapes fixed.
#define Bv   16
#define Nv   900
#define Dv   256
#define QMv  4
#define QPv  4
#define NPv  6
#define Tv   4
#define TM1v 3

// Region sizes (float elements)
#define S_MQ  (Bv*QMv*Nv*Dv)   /* 3,686,400 */
#define S_PQ  (Bv*QPv*NPv*Dv)  /*    98,304 */
#define S_EQ  (Bv*QPv*Dv)      /*    16,384 */
#define S_PER (Bv*QMv)         /*        64 */
#define S_MM  (Bv*TM1v*Nv)     /*    43,200 */
#define S_ME  (Bv*TM1v*Nv*Dv)  /* 11,059,200 */
#define S_PM  (Bv*TM1v)        /*        48 */
#define S_PE  (Bv*TM1v*Dv)     /*    12,288 */

// Output offsets
#define O_MQ  0
#define O_PQ  (O_MQ + S_MQ)
#define O_EQ  (O_PQ + S_PQ)
#define O_PER (O_EQ + S_EQ)
#define O_MM  (O_PER + S_PER)
#define O_ME  (O_MM + S_MM)
#define O_PM  (O_ME + S_ME)
#define O_PE  (O_PM + S_PM)

// Per-block chunk for linear regions: 256 threads x 4 float4 = 4096 floats
#define KITER 4
#define CHUNK (256 * KITER * 4)

// me region: input-sequential blocks. Each block: fixed b, 4 consecutive n,
// reads tae[b, n, 0..2, :] as 3KB-contiguous runs; writes 3 n-contiguous
// streams (one per t). 4 n * 3 t * 256 d = 3072 floats = 768 float4 per block.
#define ME_NB      4
#define ME_NGROUPS (Nv / ME_NB)            /* 225 */
#define B_ME       (Bv * ME_NGROUPS)       /* 3600 */

#define B_MQ  (S_MQ / CHUNK)              /* 900 exact  */
#define B_PQ  (S_PQ / CHUNK)              /* 24 exact   */
#define B_EQ  (S_EQ / CHUNK)              /* 4 exact    */
#define B_PER 1
#define B_MM  ((S_MM + CHUNK - 1)/CHUNK)  /* 11, tail   */
#define B_PM  1
#define B_PE  (S_PE / CHUNK)              /* 3 exact    */

#define E_MQ  (B_MQ)
#define E_PQ  (E_MQ + B_PQ)
#define E_EQ  (E_PQ + B_EQ)
#define E_PER (E_EQ + B_PER)
#define E_MM  (E_PER + B_MM)
#define E_ME  (E_MM + B_ME)
#define E_PM  (E_ME + B_PM)
#define E_PE  (E_PM + B_PE)
#define NBLOCKS E_PE

__global__ __launch_bounds__(256) void state_queue_kernel(
    const float* __restrict__ motion_query,      // (B,N,D)
    const float* __restrict__ plan_query,        // (B,NP,D)
    const float* __restrict__ ego_status,        // (B,D)
    const float* __restrict__ motion_queue,      // (B,QM,N,D)
    const float* __restrict__ plan_queue,        // (B,QP,NP,D)
    const float* __restrict__ ego_status_queue,  // (B,QP,D)
    const int*   __restrict__ period,            // (B,QM)
    const int*   __restrict__ mask,              // (B,) bool->int32
    const float* __restrict__ tae,               // (B,N,T,D)
    const int*   __restrict__ tm,                // (B,N,T) bool->int32
    const float* __restrict__ etae,              // (B,1,T,D)
    const int*   __restrict__ etm,               // (B,1,T) bool->int32
    float* __restrict__ out)
{
    const int blk = blockIdx.x;
    const int tid = threadIdx.x;

    if (blk < E_MQ) {
        // ---- mq: (b,q,n,d) = keep ? motion_queue : motion_query[b,n,d]
        const int base = blk * CHUNK;
        float4 v[KITER];
        #pragma unroll
        for (int k = 0; k < KITER; k++) {
            int e = base + (k * 256 + tid) * 4;
            int d = e & (Dv - 1);
            int r = e >> 8;
            int n = r % Nv;
            int b = r / (Nv * QMv);
            const float* src = (mask[b] != 0)
                ? &motion_queue[e]
                : &motion_query[(b * Nv + n) * Dv + d];
            v[k] = *reinterpret_cast<const float4*>(src);
        }
        #pragma unroll
        for (int k = 0; k < KITER; k++) {
            int e = base + (k * 256 + tid) * 4;
            *reinterpret_cast<float4*>(&out[O_MQ + e]) = v[k];
        }
    } else if (blk < E_PQ) {
        // ---- pq
        const int base = (blk - E_MQ) * CHUNK;
        float4 v[KITER];
        #pragma unroll
        for (int k = 0; k < KITER; k++) {
            int e = base + (k * 256 + tid) * 4;
            int d = e & (Dv - 1);
            int r = e >> 8;
            int np = r % NPv;
            int b = r / (NPv * QPv);
            const float* src = (mask[b] != 0)
                ? &plan_queue[e]
                : &plan_query[(b * NPv + np) * Dv + d];
            v[k] = *reinterpret_cast<const float4*>(src);
        }
        #pragma unroll
        for (int k = 0; k < KITER; k++) {
            int e = base + (k * 256 + tid) * 4;
            *reinterpret_cast<float4*>(&out[O_PQ + e]) = v[k];
        }
    } else if (blk < E_EQ) {
        // ---- eq
        const int base = (blk - E_PQ) * CHUNK;
        float4 v[KITER];
        #pragma unroll
        for (int k = 0; k < KITER; k++) {
            int e = base + (k * 256 + tid) * 4;
            int d = e & (Dv - 1);
            int b = (e >> 8) / QPv;
            const float* src = (mask[b] != 0)
                ? &ego_status_queue[e]
                : &ego_status[b * Dv + d];
            v[k] = *reinterpret_cast<const float4*>(src);
        }
        #pragma unroll
        for (int k = 0; k < KITER; k++) {
            int e = base + (k * 256 + tid) * 4;
            *reinterpret_cast<float4*>(&out[O_EQ + e]) = v[k];
        }
    } else if (blk < E_PER) {
        // ---- per: 64 elems, QM=4 per b
        int e = tid * 4;
        if (e < S_PER) {
            int b = e >> 2;  // QM = 4
            bool keep = (mask[b] != 0);
            float4 v;
            v.x = keep ? (float)period[e + 0] : 0.0f;
            v.y = keep ? (float)period[e + 1] : 0.0f;
            v.z = keep ? (float)period[e + 2] : 0.0f;
            v.w = keep ? (float)period[e + 3] : 0.0f;
            *reinterpret_cast<float4*>(&out[O_PER + e]) = v;
        }
    } else if (blk < E_MM) {
        // ---- mm: out[b][t][n] = tm[b][n][t]
        const int base = (blk - E_PER) * CHUNK;
        #pragma unroll
        for (int k = 0; k < KITER; k++) {
            int e = base + (k * 256 + tid) * 4;
            if (e < S_MM) {
                int n = e % Nv;             // N divisible by 4: same t,b for 4
                int r = e / Nv;
                int t = r % TM1v;
                int b = r / TM1v;
                int src = (b * Nv + n) * Tv + t;
                float4 v;
                v.x = tm[src + 0 * Tv] ? 1.0f : 0.0f;
                v.y = tm[src + 1 * Tv] ? 1.0f : 0.0f;
                v.z = tm[src + 2 * Tv] ? 1.0f : 0.0f;
                v.w = tm[src + 3 * Tv] ? 1.0f : 0.0f;
                *reinterpret_cast<float4*>(&out[O_MM + e]) = v;
            }
        }
    } else if (blk < E_ME) {
        // ---- me (input-sequential): block = (b, n0..n0+3)
        // out[b][t][n][d] = tae[b][n][t][d], t in 0..2
        const int mblk = blk - E_MM;
        const int b  = mblk / ME_NGROUPS;
        const int n0 = (mblk % ME_NGROUPS) * ME_NB;
        // j = k*256 + tid, j in [0, 768): n_local = j/192, t = (j%192)/64, d4 = j%64
        float4 v[3];
        int din[3], dout[3];
        #pragma unroll
        for (int k = 0; k < 3; k++) {
            int j = k * 256 + tid;
            int n_local = j / 192;
            int rem = j - n_local * 192;
            int t = rem / 64;
            int d4 = rem - t * 64;
            int n = n0 + n_local;
            din[k]  = (((b * Nv + n) * Tv + t) << 8) + d4 * 4;
            dout[k] = O_ME + (((b * TM1v + t) * Nv + n) << 8) + d4 * 4;
        }
        #pragma unroll
        for (int k = 0; k < 3; k++)
            v[k] = *reinterpret_cast<const float4*>(&tae[din[k]]);
        #pragma unroll
        for (int k = 0; k < 3; k++)
            *reinterpret_cast<float4*>(&out[dout[k]]) = v[k];
    } else if (blk < E_PM) {
        // ---- pm: 48 elems, out[b][t] = etm[b][t]
        int e = tid * 4;
        if (e < S_PM) {
            float vv[4];
            #pragma unroll
            for (int j = 0; j < 4; j++) {
                int idx = e + j;
                int t = idx % TM1v;
                int b = idx / TM1v;
                vv[j] = etm[b * Tv + t] ? 1.0f : 0.0f;
            }
            float4 v = {vv[0], vv[1], vv[2], vv[3]};
            *reinterpret_cast<float4*>(&out[O_PM + e]) = v;
        }
    } else {
        // ---- pe: out[b][t][0][d] with any/all/argmin overwrite
        const int base = (blk - E_PM) * CHUNK;
        bool anyf = false;
        #pragma unroll
        for (int bb = 0; bb < Bv; bb++)
            #pragma unroll
            for (int tt = 0; tt < TM1v; tt++)
                anyf = anyf || (etm[bb * Tv + tt] != 0);
        #pragma unroll
        for (int k = 0; k < KITER; k++) {
            int e = base + (k * 256 + tid) * 4;
            int d = e & (Dv - 1);
            int r = e >> 8;
            int t = r % TM1v;
            int b = r / TM1v;
            bool m0 = etm[b * Tv + 0] != 0;
            bool m1 = etm[b * Tv + 1] != 0;
            bool m2 = etm[b * Tv + 2] != 0;
            bool all_true = m0 && m1 && m2;
            int ff = (!m0) ? 0 : ((!m1) ? 1 : ((!m2) ? 2 : 0));
            bool overwrite = all_true || (t < ff);
            int src_t = (anyf && overwrite) ? (all_true ? (Tv - 1) : ff) : t;
            float4 v = *reinterpret_cast<const float4*>(
                &etae[(b * Tv + src_t) * Dv + d]);
            *reinterpret_cast<float4*>(&out[O_PE + e]) = v;
        }
    }
}

extern "C" void kernel_launch(void* const* d_in, const int* in_sizes, int n_in,
                              void* d_out, int out_size) {
    const float* motion_query     = (const float*)d_in[0];
    const float* plan_query       = (const float*)d_in[1];
    const float* ego_status       = (const float*)d_in[2];
    const float* motion_queue     = (const float*)d_in[3];
    const float* plan_queue       = (const float*)d_in[4];
    const float* ego_status_queue = (const float*)d_in[5];
    const int*   period           = (const int*)d_in[6];
    const int*   mask             = (const int*)d_in[7];
    const float* tae              = (const float*)d_in[8];
    const int*   tm               = (const int*)d_in[9];
    const float* etae             = (const float*)d_in[10];
    const int*   etm              = (const int*)d_in[11];
    float* out = (float*)d_out;

    state_queue_kernel<<<NBLOCKS, 256>>>(
        motion_query, plan_query, ego_status, motion_queue, plan_queue,
        ego_status_queue, period, mask, tae, tm, etae, etm, out);
}

// round 10
// speedup vs baseline: 1.1188x; 1.0009x over previous
#include <cuda_runtime.h>
#include <cstdint>

// StateQueue: pure data movement. Shapes fixed.
#define Bv   16
#define Nv   900
#define Dv   256
#define QMv  4
#define QPv  4
#define NPv  6
#define Tv   4
#define TM1v 3

// Region sizes (float elements)
#define S_MQ  (Bv*QMv*Nv*Dv)   /* 3,686,400 */
#define S_PQ  (Bv*QPv*NPv*Dv)  /*    98,304 */
#define S_EQ  (Bv*QPv*Dv)      /*    16,384 */
#define S_PER (Bv*QMv)         /*        64 */
#define S_MM  (Bv*TM1v*Nv)     /*    43,200 */
#define S_ME  (Bv*TM1v*Nv*Dv)  /* 11,059,200 */
#define S_PM  (Bv*TM1v)        /*        48 */
#define S_PE  (Bv*TM1v*Dv)     /*    12,288 */

// Output offsets
#define O_MQ  0
#define O_PQ  (O_MQ + S_MQ)
#define O_EQ  (O_PQ + S_PQ)
#define O_PER (O_EQ + S_EQ)
#define O_MM  (O_PER + S_PER)
#define O_ME  (O_MM + S_MM)
#define O_PM  (O_ME + S_ME)
#define O_PE  (O_PM + S_PM)

// Per-block chunk: 256 threads x 2 iters x 8 floats (32B) = 4096 floats
#define KV8   2
#define CHUNK (256 * KV8 * 8)
// mm/pe keep float4 x 4 iters over the same CHUNK
#define KITER 4

#define B_MQ  (S_MQ / CHUNK)              /* 900 exact  */
#define B_PQ  (S_PQ / CHUNK)              /* 24 exact   */
#define B_EQ  (S_EQ / CHUNK)              /* 4 exact    */
#define B_PER 1
#define B_MM  ((S_MM + CHUNK - 1)/CHUNK)  /* 11, tail   */
#define B_ME  (S_ME / CHUNK)              /* 2700 exact */
#define B_PM  1
#define B_PE  (S_PE / CHUNK)              /* 3 exact    */

#define E_MQ  (B_MQ)
#define E_PQ  (E_MQ + B_PQ)
#define E_EQ  (E_PQ + B_EQ)
#define E_PER (E_EQ + B_PER)
#define E_MM  (E_PER + B_MM)
#define E_ME  (E_MM + B_ME)
#define E_PM  (E_ME + B_PM)
#define E_PE  (E_PM + B_PE)
#define NBLOCKS E_PE

// 256-bit global load/store (sm_100+: LDG.E.256 / STG.E.256)
__device__ __forceinline__ void ldg_v8(const float* p, uint32_t* r) {
    asm volatile("ld.global.v8.b32 {%0,%1,%2,%3,%4,%5,%6,%7}, [%8];"
        : "=r"(r[0]), "=r"(r[1]), "=r"(r[2]), "=r"(r[3]),
          "=r"(r[4]), "=r"(r[5]), "=r"(r[6]), "=r"(r[7])
        : "l"(p));
}
__device__ __forceinline__ void stg_v8(float* p, const uint32_t* r) {
    asm volatile("st.global.v8.b32 [%0], {%1,%2,%3,%4,%5,%6,%7,%8};"
        :: "l"(p),
           "r"(r[0]), "r"(r[1]), "r"(r[2]), "r"(r[3]),
           "r"(r[4]), "r"(r[5]), "r"(r[6]), "r"(r[7])
        : "memory");
}

__global__ __launch_bounds__(256) void state_queue_kernel(
    const float* __restrict__ motion_query,      // (B,N,D)
    const float* __restrict__ plan_query,        // (B,NP,D)
    const float* __restrict__ ego_status,        // (B,D)
    const float* __restrict__ motion_queue,      // (B,QM,N,D)
    const float* __restrict__ plan_queue,        // (B,QP,NP,D)
    const float* __restrict__ ego_status_queue,  // (B,QP,D)
    const int*   __restrict__ period,            // (B,QM)
    const int*   __restrict__ mask,              // (B,) bool->int32
    const float* __restrict__ tae,               // (B,N,T,D)
    const int*   __restrict__ tm,                // (B,N,T) bool->int32
    const float* __restrict__ etae,              // (B,1,T,D)
    const int*   __restrict__ etm,               // (B,1,T) bool->int32
    float* __restrict__ out)
{
    const int blk = blockIdx.x;
    const int tid = threadIdx.x;

    if (blk < E_MQ) {
        // ---- mq: (b,q,n,d) = keep ? motion_queue : motion_query[b,n,d]
        const int base = blk * CHUNK;
        uint32_t v[KV8][8];
        #pragma unroll
        for (int k = 0; k < KV8; k++) {
            int e = base + (k * 256 + tid) * 8;
            int d = e & (Dv - 1);
            int r = e >> 8;
            int n = r % Nv;
            int b = r / (Nv * QMv);
            const float* src = (mask[b] != 0)
                ? &motion_queue[e]
                : &motion_query[(b * Nv + n) * Dv + d];
            ldg_v8(src, v[k]);
        }
        #pragma unroll
        for (int k = 0; k < KV8; k++) {
            int e = base + (k * 256 + tid) * 8;
            stg_v8(&out[O_MQ + e], v[k]);
        }
    } else if (blk < E_PQ) {
        // ---- pq
        const int base = (blk - E_MQ) * CHUNK;
        uint32_t v[KV8][8];
        #pragma unroll
        for (int k = 0; k < KV8; k++) {
            int e = base + (k * 256 + tid) * 8;
            int d = e & (Dv - 1);
            int r = e >> 8;
            int np = r % NPv;
            int b = r / (NPv * QPv);
            const float* src = (mask[b] != 0)
                ? &plan_queue[e]
                : &plan_query[(b * NPv + np) * Dv + d];
            ldg_v8(src, v[k]);
        }
        #pragma unroll
        for (int k = 0; k < KV8; k++) {
            int e = base + (k * 256 + tid) * 8;
            stg_v8(&out[O_PQ + e], v[k]);
        }
    } else if (blk < E_EQ) {
        // ---- eq
        const int base = (blk - E_PQ) * CHUNK;
        uint32_t v[KV8][8];
        #pragma unroll
        for (int k = 0; k < KV8; k++) {
            int e = base + (k * 256 + tid) * 8;
            int d = e & (Dv - 1);
            int b = (e >> 8) / QPv;
            const float* src = (mask[b] != 0)
                ? &ego_status_queue[e]
                : &ego_status[b * Dv + d];
            ldg_v8(src, v[k]);
        }
        #pragma unroll
        for (int k = 0; k < KV8; k++) {
            int e = base + (k * 256 + tid) * 8;
            stg_v8(&out[O_EQ + e], v[k]);
        }
    } else if (blk < E_PER) {
        // ---- per: 64 elems, QM=4 per b
        int e = tid * 4;
        if (e < S_PER) {
            int b = e >> 2;  // QM = 4
            bool keep = (mask[b] != 0);
            float4 v;
            v.x = keep ? (float)period[e + 0] : 0.0f;
            v.y = keep ? (float)period[e + 1] : 0.0f;
            v.z = keep ? (float)period[e + 2] : 0.0f;
            v.w = keep ? (float)period[e + 3] : 0.0f;
            *reinterpret_cast<float4*>(&out[O_PER + e]) = v;
        }
    } else if (blk < E_MM) {
        // ---- mm: out[b][t][n] = tm[b][n][t]
        const int base = (blk - E_PER) * CHUNK;
        #pragma unroll
        for (int k = 0; k < KITER; k++) {
            int e = base + (k * 256 + tid) * 4;
            if (e < S_MM) {
                int n = e % Nv;             // N divisible by 4: same t,b for 4
                int r = e / Nv;
                int t = r % TM1v;
                int b = r / TM1v;
                int src = (b * Nv + n) * Tv + t;
                float4 v;
                v.x = tm[src + 0 * Tv] ? 1.0f : 0.0f;
                v.y = tm[src + 1 * Tv] ? 1.0f : 0.0f;
                v.z = tm[src + 2 * Tv] ? 1.0f : 0.0f;
                v.w = tm[src + 3 * Tv] ? 1.0f : 0.0f;
                *reinterpret_cast<float4*>(&out[O_MM + e]) = v;
            }
        }
    } else if (blk < E_ME) {
        // ---- me: out[b][t][n][d] = tae[b][n][t][d]
        const int base = (blk - E_MM) * CHUNK;
        uint32_t v[KV8][8];
        #pragma unroll
        for (int k = 0; k < KV8; k++) {
            int e = base + (k * 256 + tid) * 8;
            int d = e & (Dv - 1);
            int r = e >> 8;
            int n = r % Nv;
            int t = (r / Nv) % TM1v;
            int b = r / (Nv * TM1v);
            ldg_v8(&tae[((b * Nv + n) * Tv + t) * Dv + d], v[k]);
        }
        #pragma unroll
        for (int k = 0; k < KV8; k++) {
            int e = base + (k * 256 + tid) * 8;
            stg_v8(&out[O_ME + e], v[k]);
        }
    } else if (blk < E_PM) {
        // ---- pm: 48 elems, out[b][t] = etm[b][t]
        int e = tid * 4;
        if (e < S_PM) {
            float vv[4];
            #pragma unroll
            for (int j = 0; j < 4; j++) {
                int idx = e + j;
                int t = idx % TM1v;
                int b = idx / TM1v;
                vv[j] = etm[b * Tv + t] ? 1.0f : 0.0f;
            }
            float4 v = {vv[0], vv[1], vv[2], vv[3]};
            *reinterpret_cast<float4*>(&out[O_PM + e]) = v;
        }
    } else {
        // ---- pe: out[b][t][0][d] with any/all/argmin overwrite
        const int base = (blk - E_PM) * CHUNK;
        bool anyf = false;
        #pragma unroll
        for (int bb = 0; bb < Bv; bb++)
            #pragma unroll
            for (int tt = 0; tt < TM1v; tt++)
                anyf = anyf || (etm[bb * Tv + tt] != 0);
        #pragma unroll
        for (int k = 0; k < KITER; k++) {
            int e = base + (k * 256 + tid) * 4;
            int d = e & (Dv - 1);
            int r = e >> 8;
            int t = r % TM1v;
            int b = r / TM1v;
            bool m0 = etm[b * Tv + 0] != 0;
            bool m1 = etm[b * Tv + 1] != 0;
            bool m2 = etm[b * Tv + 2] != 0;
            bool all_true = m0 && m1 && m2;
            int ff = (!m0) ? 0 : ((!m1) ? 1 : ((!m2) ? 2 : 0));
            bool overwrite = all_true || (t < ff);
            int src_t = (anyf && overwrite) ? (all_true ? (Tv - 1) : ff) : t;
            float4 v = *reinterpret_cast<const float4*>(
                &etae[(b * Tv + src_t) * Dv + d]);
            *reinterpret_cast<float4*>(&out[O_PE + e]) = v;
        }
    }
}

extern "C" void kernel_launch(void* const* d_in, const int* in_sizes, int n_in,
                              void* d_out, int out_size) {
    const float* motion_query     = (const float*)d_in[0];
    const float* plan_query       = (const float*)d_in[1];
    const float* ego_status       = (const float*)d_in[2];
    const float* motion_queue     = (const float*)d_in[3];
    const float* plan_queue       = (const float*)d_in[4];
    const float* ego_status_queue = (const float*)d_in[5];
    const int*   period           = (const int*)d_in[6];
    const int*   mask             = (const int*)d_in[7];
    const float* tae              = (const float*)d_in[8];
    const int*   tm               = (const int*)d_in[9];
    const float* etae             = (const float*)d_in[10];
    const int*   etm              = (const int*)d_in[11];
    float* out = (float*)d_out;

    state_queue_kernel<<<NBLOCKS, 256>>>(
        motion_query, plan_query, ego_status, motion_queue, plan_queue,
        ego_status_queue, period, mask, tae, tm, etae, etm, out);
}